// round 2
// baseline (speedup 1.0000x reference)
#include <cuda_runtime.h>
#include <cuda_bf16.h>

// Problem constants
#define Bb_  4
#define T_   128
#define V_   50257
#define LSRC 512
#define D_   512
#define MROWS 512              // B*T
#define KPAD 50304             // 786 * 64
#define KTILES 786
#define KSLICES 16

// Scratch (static device memory: allowed)
__device__ __nv_bfloat16 g_Ab[(size_t)MROWS * KPAD];   // exp(X), bf16, zero-padded
__device__ __nv_bfloat16 g_Bt[(size_t)D_ * KPAD];      // W^T, bf16, zero-padded
__device__ float g_U[MROWS * D_];                       // GEMM output
__device__ float g_scal[8];  // 0:cov_sum 1:nll_sum 2:valid_cnt 3:cos_sum

__device__ __forceinline__ float warp_sum(float v) {
    #pragma unroll
    for (int o = 16; o > 0; o >>= 1) v += __shfl_xor_sync(0xffffffffu, v, o);
    return v;
}

// ---------------- zero scratch ----------------
__global__ void zero_kernel() {
    for (int i = blockIdx.x * blockDim.x + threadIdx.x; i < MROWS * D_;
         i += gridDim.x * blockDim.x)
        g_U[i] = 0.f;
    if (blockIdx.x == 0 && threadIdx.x < 8) g_scal[threadIdx.x] = 0.f;
}

// ---------------- A = exp(X) in bf16, padded ----------------
__global__ void convert_expX_kernel(const float* __restrict__ X) {
    int row = blockIdx.y;
    int col = blockIdx.x * blockDim.x + threadIdx.x;
    if (col >= KPAD) return;
    float v = 0.f;
    if (col < V_) v = __expf(X[(size_t)row * V_ + col]);
    g_Ab[(size_t)row * KPAD + col] = __float2bfloat16(v);
}

// ---------------- B = W^T in bf16, padded ----------------
__global__ void transpose_w_kernel(const float* __restrict__ W) {
    __shared__ float tile[32][33];
    int v0 = blockIdx.x * 32;
    int d0 = blockIdx.y * 32;
    int tx = threadIdx.x, ty = threadIdx.y;
    int v = v0 + ty;
    tile[ty][tx] = (v < V_) ? W[(size_t)v * D_ + d0 + tx] : 0.f;
    __syncthreads();
    g_Bt[(size_t)(d0 + ty) * KPAD + v0 + tx] = __float2bfloat16(tile[tx][ty]);
}

// ---------------- split-K bf16 mma GEMM: U += expX @ W ----------------
__device__ __forceinline__ void mma16816(float* c, const unsigned* a, const unsigned* b) {
    asm volatile(
        "mma.sync.aligned.m16n8k16.row.col.f32.bf16.bf16.f32 "
        "{%0,%1,%2,%3}, {%4,%5,%6,%7}, {%8,%9}, {%0,%1,%2,%3};\n"
        : "+f"(c[0]), "+f"(c[1]), "+f"(c[2]), "+f"(c[3])
        : "r"(a[0]), "r"(a[1]), "r"(a[2]), "r"(a[3]), "r"(b[0]), "r"(b[1]));
}

__global__ __launch_bounds__(256) void gemm_kernel() {
    __shared__ __nv_bfloat16 sA[128][72];
    __shared__ __nv_bfloat16 sB[128][72];
    const int bm = blockIdx.y * 128;
    const int bn = blockIdx.x * 128;
    const int tilesPer = (KTILES + KSLICES - 1) / KSLICES;     // 50
    int t0 = blockIdx.z * tilesPer;
    int t1 = min(KTILES, t0 + tilesPer);
    const int tid = threadIdx.x;
    const int warp = tid >> 5, lane = tid & 31;
    const int wm = (warp >> 2) * 64;     // 2 warp rows
    const int wn = (warp & 3) * 32;      // 4 warp cols
    const int g = lane >> 2, q = lane & 3;

    float acc[4][4][4];
    #pragma unroll
    for (int i = 0; i < 4; i++)
        #pragma unroll
        for (int j = 0; j < 4; j++)
            #pragma unroll
            for (int k = 0; k < 4; k++) acc[i][j][k] = 0.f;

    for (int kt = t0; kt < t1; ++kt) {
        const int k0 = kt * 64;
        #pragma unroll
        for (int r = 0; r < 4; ++r) {
            int v = tid + r * 256;            // 0..1023
            int row = v >> 3, c8 = (v & 7) * 8;
            *reinterpret_cast<uint4*>(&sA[row][c8]) =
                *reinterpret_cast<const uint4*>(&g_Ab[(size_t)(bm + row) * KPAD + k0 + c8]);
            *reinterpret_cast<uint4*>(&sB[row][c8]) =
                *reinterpret_cast<const uint4*>(&g_Bt[(size_t)(bn + row) * KPAD + k0 + c8]);
        }
        __syncthreads();
        #pragma unroll
        for (int kk = 0; kk < 4; ++kk) {
            const int kb = kk * 16 + q * 2;
            unsigned af[4][4];
            #pragma unroll
            for (int mf = 0; mf < 4; ++mf) {
                int r = wm + mf * 16 + g;
                af[mf][0] = *reinterpret_cast<const unsigned*>(&sA[r][kb]);
                af[mf][1] = *reinterpret_cast<const unsigned*>(&sA[r + 8][kb]);
                af[mf][2] = *reinterpret_cast<const unsigned*>(&sA[r][kb + 8]);
                af[mf][3] = *reinterpret_cast<const unsigned*>(&sA[r + 8][kb + 8]);
            }
            unsigned bfr[4][2];
            #pragma unroll
            for (int nf = 0; nf < 4; ++nf) {
                int r = wn + nf * 8 + g;
                bfr[nf][0] = *reinterpret_cast<const unsigned*>(&sB[r][kb]);
                bfr[nf][1] = *reinterpret_cast<const unsigned*>(&sB[r][kb + 8]);
            }
            #pragma unroll
            for (int mf = 0; mf < 4; ++mf)
                #pragma unroll
                for (int nf = 0; nf < 4; ++nf)
                    mma16816(acc[mf][nf], af[mf], bfr[nf]);
        }
        __syncthreads();
    }

    #pragma unroll
    for (int mf = 0; mf < 4; ++mf) {
        int r0 = bm + wm + mf * 16 + g;
        #pragma unroll
        for (int nf = 0; nf < 4; ++nf) {
            int c0 = bn + wn + nf * 8 + q * 2;
            atomicAdd(&g_U[r0 * D_ + c0],           acc[mf][nf][0]);
            atomicAdd(&g_U[r0 * D_ + c0 + 1],       acc[mf][nf][1]);
            atomicAdd(&g_U[(r0 + 8) * D_ + c0],     acc[mf][nf][2]);
            atomicAdd(&g_U[(r0 + 8) * D_ + c0 + 1], acc[mf][nf][3]);
        }
    }
}

// ---------------- coverage loss partial ----------------
__global__ void cov_kernel(const float* __restrict__ attn,
                           const float* __restrict__ covg,
                           const int* __restrict__ mask) {
    float s = 0.f;
    const int total = Bb_ * LSRC * T_;   // 262144
    for (int idx = blockIdx.x * blockDim.x + threadIdx.x; idx < total;
         idx += gridDim.x * blockDim.x) {
        int t = idx & (T_ - 1);
        int b = idx >> 16;               // 512*128 = 65536 per batch
        if (mask[(b << 7) + t] == 0) s += fminf(attn[idx], covg[idx]);
    }
    s = warp_sum(s);
    __shared__ float sm[8];
    int warp = threadIdx.x >> 5, lane = threadIdx.x & 31;
    if (lane == 0) sm[warp] = s;
    __syncthreads();
    if (threadIdx.x == 0) {
        float tot = 0.f;
        for (int w = 0; w < (int)(blockDim.x >> 5); ++w) tot += sm[w];
        atomicAdd(&g_scal[0], tot);
    }
}

// ---------------- NLL partials ----------------
__global__ void nll_kernel(const float* __restrict__ X, const int* __restrict__ trg) {
    int i = threadIdx.x;  // 512 threads, 1 block
    float s = 0.f, c = 0.f;
    int tg = trg[i];
    if (tg != 0) {
        s = logf(X[(size_t)i * V_ + tg]);
        c = 1.f;
    }
    s = warp_sum(s);
    c = warp_sum(c);
    __shared__ float sms[16], smc[16];
    int warp = threadIdx.x >> 5, lane = threadIdx.x & 31;
    if (lane == 0) { sms[warp] = s; smc[warp] = c; }
    __syncthreads();
    if (threadIdx.x == 0) {
        float ts = 0.f, tc = 0.f;
        for (int w = 0; w < 16; ++w) { ts += sms[w]; tc += smc[w]; }
        atomicAdd(&g_scal[1], ts);
        atomicAdd(&g_scal[2], tc);
    }
}

// ---------------- per-row cosine (OT) ----------------
__global__ void finalize_kernel(const int* __restrict__ trg, const float* __restrict__ W) {
    int i = blockIdx.x;                  // 512 rows
    int tid = threadIdx.x;               // 128 threads
    int tg = trg[i];
    const float* U = &g_U[i * D_];
    const float* E = &W[(size_t)tg * D_];
    float sue = 0.f, suu = 0.f, see = 0.f;
    for (int d = tid; d < D_; d += 128) {
        float u = U[d], e = E[d];
        sue += u * e; suu += u * u; see += e * e;
    }
    sue = warp_sum(sue); suu = warp_sum(suu); see = warp_sum(see);
    __shared__ float sm[3][4];
    int warp = tid >> 5, lane = tid & 31;
    if (lane == 0) { sm[0][warp] = sue; sm[1][warp] = suu; sm[2][warp] = see; }
    __syncthreads();
    if (tid == 0) {
        float a = sm[0][0] + sm[0][1] + sm[0][2] + sm[0][3];
        float b = sm[1][0] + sm[1][1] + sm[1][2] + sm[1][3];
        float c = sm[2][0] + sm[2][1] + sm[2][2] + sm[2][3];
        atomicAdd(&g_scal[3], a * rsqrtf(b * c));
    }
}

// ---------------- combine ----------------
__global__ void combine_kernel(const int* __restrict__ dec_len, float* __restrict__ out) {
    int ls = dec_len[0] + dec_len[1] + dec_len[2] + dec_len[3];
    float nll = -g_scal[1] / g_scal[2];
    float cov_loss = g_scal[0] / (float)ls;
    float ot = g_scal[3] / (float)MROWS;
    out[0] = nll + 1.0f * cov_loss + 0.1f + ot;
}

extern "C" void kernel_launch(void* const* d_in, const int* in_sizes, int n_in,
                              void* d_out, int out_size) {
    const float* X    = (const float*)d_in[0];   // output_mle [4,128,50257]
    const float* attn = (const float*)d_in[1];   // [4,512,128]
    const float* covg = (const float*)d_in[2];   // [4,512,128]
    const int*   trg  = (const int*)d_in[3];     // [4,128]
    const int*   mask = (const int*)d_in[4];     // dec_mask [4,128]
    const int*   dlen = (const int*)d_in[5];     // [4]
    const float* W    = (const float*)d_in[6];   // [50257,512]
    float* out = (float*)d_out;

    zero_kernel<<<256, 256>>>();
    {
        dim3 grid((KPAD + 255) / 256, MROWS);
        convert_expX_kernel<<<grid, 256>>>(X);
    }
    {
        dim3 grid(KPAD / 32, D_ / 32);  // 1572 x 16
        transpose_w_kernel<<<grid, dim3(32, 32)>>>(W);
    }
    {
        dim3 grid(4, 4, KSLICES);
        gemm_kernel<<<grid, 256>>>();
    }
    cov_kernel<<<128, 256>>>(attn, covg, mask);
    nll_kernel<<<1, 512>>>(X, trg);
    finalize_kernel<<<512, 128>>>(trg, W);
    combine_kernel<<<1, 1>>>(dlen, out);
}

// round 3
// speedup vs baseline: 1.1471x; 1.1471x over previous
#include <cuda_runtime.h>
#include <cuda_bf16.h>

// Problem constants
#define Bb_  4
#define T_   128
#define V_   50257
#define LSRC 512
#define D_   512
#define MROWS 512              // B*T
#define KTILES 786             // ceil(50257/64)
#define KSLICES 9              // 4*4*9 = 144 CTAs = 1 wave on 148 SMs

__device__ float g_U[MROWS * D_];   // GEMM output (split-K accumulated)
__device__ float g_scal[8];         // 0:cov_sum 1:nll_sum 2:valid_cnt 3:cos_sum

__device__ __forceinline__ float warp_sum(float v) {
    #pragma unroll
    for (int o = 16; o > 0; o >>= 1) v += __shfl_xor_sync(0xffffffffu, v, o);
    return v;
}

// ---------------- zero scratch ----------------
__global__ void zero_kernel() {
    for (int i = blockIdx.x * blockDim.x + threadIdx.x; i < MROWS * D_;
         i += gridDim.x * blockDim.x)
        g_U[i] = 0.f;
    if (blockIdx.x == 0 && threadIdx.x < 8) g_scal[threadIdx.x] = 0.f;
}

// ---------------- fused split-K bf16 GEMM: U += exp(X) @ W ----------------
__device__ __forceinline__ void mma16816(float* c, const unsigned* a, const unsigned* b) {
    asm volatile(
        "mma.sync.aligned.m16n8k16.row.col.f32.bf16.bf16.f32 "
        "{%0,%1,%2,%3}, {%4,%5,%6,%7}, {%8,%9}, {%0,%1,%2,%3};\n"
        : "+f"(c[0]), "+f"(c[1]), "+f"(c[2]), "+f"(c[3])
        : "r"(a[0]), "r"(a[1]), "r"(a[2]), "r"(a[3]), "r"(b[0]), "r"(b[1]));
}

// Load one 128x64 A tile (exp of X, fp32->regs) and one 64x128 W tile into regs.
__device__ __forceinline__ void load_regs(
    const float* __restrict__ X, const float* __restrict__ W,
    int bm, int bn, int k0, int tid,
    float* av, float4* bv0, float4* bv1)
{
    if (k0 + 64 <= V_) {
        #pragma unroll
        for (int i = 0; i < 32; ++i) {
            int e = tid + (i << 8);
            int row = e >> 6, col = e & 63;
            av[i] = __expf(__ldg(&X[(size_t)(bm + row) * V_ + k0 + col]));
        }
        #pragma unroll
        for (int i = 0; i < 4; ++i) {
            int p = tid + (i << 8);
            int kp = p >> 5, n4 = p & 31;
            const float* wp = &W[(size_t)(k0 + 2 * kp) * D_ + bn + n4 * 4];
            bv0[i] = *(const float4*)wp;
            bv1[i] = *(const float4*)(wp + D_);
        }
    } else {  // partial last K tile (17 valid cols)
        #pragma unroll
        for (int i = 0; i < 32; ++i) {
            int e = tid + (i << 8);
            int row = e >> 6, col = e & 63;
            float x = 0.f;
            if (k0 + col < V_) x = __expf(__ldg(&X[(size_t)(bm + row) * V_ + k0 + col]));
            av[i] = x;
        }
        #pragma unroll
        for (int i = 0; i < 4; ++i) {
            int p = tid + (i << 8);
            int kp = p >> 5, n4 = p & 31;
            int kr = k0 + 2 * kp;
            const float* wp = &W[(size_t)kr * D_ + bn + n4 * 4];
            bv0[i] = (kr     < V_) ? *(const float4*)wp        : make_float4(0, 0, 0, 0);
            bv1[i] = (kr + 1 < V_) ? *(const float4*)(wp + D_) : make_float4(0, 0, 0, 0);
        }
    }
}

__device__ __forceinline__ void store_smem(
    int tid, const float* av, const float4* bv0, const float4* bv1,
    __nv_bfloat16 (*sA)[72], __nv_bfloat16 (*sB)[72])
{
    #pragma unroll
    for (int i = 0; i < 32; ++i) {
        int e = tid + (i << 8);
        sA[e >> 6][e & 63] = __float2bfloat16(av[i]);
    }
    #pragma unroll
    for (int i = 0; i < 4; ++i) {
        int p = tid + (i << 8);
        int kp = p >> 5, n4 = (p & 31) * 4;
        int kb = 2 * kp;
        // sB layout is [n][k] (K-contiguous), k-pairs packed bf16x2: {W[k][n], W[k+1][n]}
        *(__nv_bfloat162*)&sB[n4 + 0][kb] = __floats2bfloat162_rn(bv0[i].x, bv1[i].x);
        *(__nv_bfloat162*)&sB[n4 + 1][kb] = __floats2bfloat162_rn(bv0[i].y, bv1[i].y);
        *(__nv_bfloat162*)&sB[n4 + 2][kb] = __floats2bfloat162_rn(bv0[i].z, bv1[i].z);
        *(__nv_bfloat162*)&sB[n4 + 3][kb] = __floats2bfloat162_rn(bv0[i].w, bv1[i].w);
    }
}

__global__ __launch_bounds__(256, 1) void gemm_fused(
    const float* __restrict__ X, const float* __restrict__ W)
{
    __shared__ __nv_bfloat16 sA[128][72];
    __shared__ __nv_bfloat16 sB[128][72];
    const int bm = blockIdx.y * 128;
    const int bn = blockIdx.x * 128;
    const int tilesPer = (KTILES + KSLICES - 1) / KSLICES;   // 88
    const int t0 = blockIdx.z * tilesPer;
    const int t1 = min(KTILES, t0 + tilesPer);
    const int tid = threadIdx.x;
    const int warp = tid >> 5, lane = tid & 31;
    const int wm = (warp >> 2) * 64;     // 2 warp rows of 64
    const int wn = (warp & 3) * 32;      // 4 warp cols of 32
    const int g = lane >> 2, q = lane & 3;

    float acc[4][4][4];
    #pragma unroll
    for (int i = 0; i < 4; i++)
        #pragma unroll
        for (int j = 0; j < 4; j++)
            #pragma unroll
            for (int k = 0; k < 4; k++) acc[i][j][k] = 0.f;

    float  av[32];
    float4 bv0[4], bv1[4];

    // prologue: tile t0 -> regs -> smem
    load_regs(X, W, bm, bn, t0 * 64, tid, av, bv0, bv1);
    store_smem(tid, av, bv0, bv1, sA, sB);
    __syncthreads();

    for (int kt = t0; kt < t1; ++kt) {
        // prefetch next tile into regs while computing current from smem
        if (kt + 1 < t1)
            load_regs(X, W, bm, bn, (kt + 1) * 64, tid, av, bv0, bv1);

        #pragma unroll
        for (int kk = 0; kk < 4; ++kk) {
            const int kb = kk * 16 + q * 2;
            unsigned af[4][4];
            #pragma unroll
            for (int mf = 0; mf < 4; ++mf) {
                int r = wm + mf * 16 + g;
                af[mf][0] = *reinterpret_cast<const unsigned*>(&sA[r][kb]);
                af[mf][1] = *reinterpret_cast<const unsigned*>(&sA[r + 8][kb]);
                af[mf][2] = *reinterpret_cast<const unsigned*>(&sA[r][kb + 8]);
                af[mf][3] = *reinterpret_cast<const unsigned*>(&sA[r + 8][kb + 8]);
            }
            unsigned bfr[4][2];
            #pragma unroll
            for (int nf = 0; nf < 4; ++nf) {
                int r = wn + nf * 8 + g;
                bfr[nf][0] = *reinterpret_cast<const unsigned*>(&sB[r][kb]);
                bfr[nf][1] = *reinterpret_cast<const unsigned*>(&sB[r][kb + 8]);
            }
            #pragma unroll
            for (int mf = 0; mf < 4; ++mf)
                #pragma unroll
                for (int nf = 0; nf < 4; ++nf)
                    mma16816(acc[mf][nf], af[mf], bfr[nf]);
        }

        if (kt + 1 < t1) {
            __syncthreads();                       // compute done, safe to overwrite
            store_smem(tid, av, bv0, bv1, sA, sB);
            __syncthreads();
        }
    }

    #pragma unroll
    for (int mf = 0; mf < 4; ++mf) {
        int r0 = bm + wm + mf * 16 + g;
        #pragma unroll
        for (int nf = 0; nf < 4; ++nf) {
            int c0 = bn + wn + nf * 8 + q * 2;
            atomicAdd(&g_U[r0 * D_ + c0],           acc[mf][nf][0]);
            atomicAdd(&g_U[r0 * D_ + c0 + 1],       acc[mf][nf][1]);
            atomicAdd(&g_U[(r0 + 8) * D_ + c0],     acc[mf][nf][2]);
            atomicAdd(&g_U[(r0 + 8) * D_ + c0 + 1], acc[mf][nf][3]);
        }
    }
}

// ---------------- coverage loss partial ----------------
__global__ void cov_kernel(const float* __restrict__ attn,
                           const float* __restrict__ covg,
                           const int* __restrict__ mask) {
    float s = 0.f;
    const int total = Bb_ * LSRC * T_;   // 262144
    for (int idx = blockIdx.x * blockDim.x + threadIdx.x; idx < total;
         idx += gridDim.x * blockDim.x) {
        int t = idx & (T_ - 1);
        int b = idx >> 16;
        if (mask[(b << 7) + t] == 0) s += fminf(attn[idx], covg[idx]);
    }
    s = warp_sum(s);
    __shared__ float sm[8];
    int warp = threadIdx.x >> 5, lane = threadIdx.x & 31;
    if (lane == 0) sm[warp] = s;
    __syncthreads();
    if (threadIdx.x == 0) {
        float tot = 0.f;
        for (int w = 0; w < (int)(blockDim.x >> 5); ++w) tot += sm[w];
        atomicAdd(&g_scal[0], tot);
    }
}

// ---------------- NLL partials ----------------
__global__ void nll_kernel(const float* __restrict__ X, const int* __restrict__ trg) {
    int i = threadIdx.x;  // 512 threads, 1 block
    float s = 0.f, c = 0.f;
    int tg = trg[i];
    if (tg != 0) {
        s = logf(X[(size_t)i * V_ + tg]);
        c = 1.f;
    }
    s = warp_sum(s);
    c = warp_sum(c);
    __shared__ float sms[16], smc[16];
    int warp = threadIdx.x >> 5, lane = threadIdx.x & 31;
    if (lane == 0) { sms[warp] = s; smc[warp] = c; }
    __syncthreads();
    if (threadIdx.x == 0) {
        float ts = 0.f, tc = 0.f;
        for (int w = 0; w < 16; ++w) { ts += sms[w]; tc += smc[w]; }
        atomicAdd(&g_scal[1], ts);
        atomicAdd(&g_scal[2], tc);
    }
}

// ---------------- per-row cosine (OT via diagonal-IPOT collapse) ----------------
__global__ void finalize_kernel(const int* __restrict__ trg, const float* __restrict__ W) {
    int i = blockIdx.x;                  // 512 rows
    int tid = threadIdx.x;               // 128 threads
    int tg = trg[i];
    const float* U = &g_U[i * D_];
    const float* E = &W[(size_t)tg * D_];
    float sue = 0.f, suu = 0.f, see = 0.f;
    for (int d = tid; d < D_; d += 128) {
        float u = U[d], e = E[d];
        sue += u * e; suu += u * u; see += e * e;
    }
    sue = warp_sum(sue); suu = warp_sum(suu); see = warp_sum(see);
    __shared__ float sm[3][4];
    int warp = tid >> 5, lane = tid & 31;
    if (lane == 0) { sm[0][warp] = sue; sm[1][warp] = suu; sm[2][warp] = see; }
    __syncthreads();
    if (tid == 0) {
        float a = sm[0][0] + sm[0][1] + sm[0][2] + sm[0][3];
        float b = sm[1][0] + sm[1][1] + sm[1][2] + sm[1][3];
        float c = sm[2][0] + sm[2][1] + sm[2][2] + sm[2][3];
        atomicAdd(&g_scal[3], a * rsqrtf(b * c));
    }
}

// ---------------- combine ----------------
__global__ void combine_kernel(const int* __restrict__ dec_len, float* __restrict__ out) {
    int ls = dec_len[0] + dec_len[1] + dec_len[2] + dec_len[3];
    float nll = -g_scal[1] / g_scal[2];
    float cov_loss = g_scal[0] / (float)ls;
    float ot = g_scal[3] / (float)MROWS;
    out[0] = nll + 1.0f * cov_loss + 0.1f + ot;
}

extern "C" void kernel_launch(void* const* d_in, const int* in_sizes, int n_in,
                              void* d_out, int out_size) {
    const float* X    = (const float*)d_in[0];   // output_mle [4,128,50257]
    const float* attn = (const float*)d_in[1];   // [4,512,128]
    const float* covg = (const float*)d_in[2];   // [4,512,128]
    const int*   trg  = (const int*)d_in[3];     // [4,128]
    const int*   mask = (const int*)d_in[4];     // dec_mask [4,128]
    const int*   dlen = (const int*)d_in[5];     // [4]
    const float* W    = (const float*)d_in[6];   // [50257,512]
    float* out = (float*)d_out;

    zero_kernel<<<256, 256>>>();
    {
        dim3 grid(4, 4, KSLICES);   // 144 CTAs = one wave
        gemm_fused<<<grid, 256>>>(X, W);
    }
    cov_kernel<<<128, 256>>>(attn, covg, mask);
    nll_kernel<<<1, 512>>>(X, trg);
    finalize_kernel<<<512, 128>>>(trg, W);
    combine_kernel<<<1, 1>>>(dlen, out);
}

// round 5
// speedup vs baseline: 1.6032x; 1.3977x over previous
#include <cuda_runtime.h>
#include <cuda_bf16.h>
#include <stdint.h>

// Problem constants
#define Bb_  4
#define T_   128
#define V_   50257
#define LSRC 512
#define D_   512
#define MROWS 512              // B*T

// GEMM tiling
#define BM 256
#define BN 128
#define BK 32
#define NTHREADS 512
#define KT2 1571               // ceil(50257/32)
#define KSL 18                 // 2*4*18 = 144 CTAs
#define TPS 88                 // ceil(1571/18)

// dynamic smem layout (bytes)
#define SX_STRIDE 8192                 // floats per X stage (256*32)
#define SW_STRIDE 4224                 // floats per W stage (32*132)
#define OFF_SW    98304                // 3 * 8192 * 4
#define OFF_SA    (OFF_SW + 3*4224*4)  // 98304 + 50688 = 148992
#define SMEM_BYTES (OFF_SA + 256*40*2) // 148992 + 20480 = 169472

__device__ float g_U[MROWS * D_];
__device__ float g_scal[8];  // 0:cov 1:nll 2:valid 3:cos

__device__ __forceinline__ float warp_sum(float v) {
    #pragma unroll
    for (int o = 16; o > 0; o >>= 1) v += __shfl_xor_sync(0xffffffffu, v, o);
    return v;
}

__device__ __forceinline__ void cp_async4(void* dst, const void* src) {
    uint32_t d = (uint32_t)__cvta_generic_to_shared(dst);
    asm volatile("cp.async.ca.shared.global [%0], [%1], 4;\n" :: "r"(d), "l"(src));
}
__device__ __forceinline__ void cp_async16(void* dst, const void* src) {
    uint32_t d = (uint32_t)__cvta_generic_to_shared(dst);
    asm volatile("cp.async.cg.shared.global [%0], [%1], 16;\n" :: "r"(d), "l"(src));
}
__device__ __forceinline__ void cp_commit() {
    asm volatile("cp.async.commit_group;\n" ::: "memory");
}
__device__ __forceinline__ void cp_wait1() {
    asm volatile("cp.async.wait_group 1;\n" ::: "memory");
}

__device__ __forceinline__ void ldmatrix_x4(unsigned* r, uint32_t addr) {
    asm volatile("ldmatrix.sync.aligned.m8n8.x4.shared.b16 {%0,%1,%2,%3}, [%4];"
                 : "=r"(r[0]), "=r"(r[1]), "=r"(r[2]), "=r"(r[3]) : "r"(addr));
}

__device__ __forceinline__ void mma16816(float* c, const unsigned* a, unsigned b0, unsigned b1) {
    asm volatile(
        "mma.sync.aligned.m16n8k16.row.col.f32.bf16.bf16.f32 "
        "{%0,%1,%2,%3}, {%4,%5,%6,%7}, {%8,%9}, {%0,%1,%2,%3};\n"
        : "+f"(c[0]), "+f"(c[1]), "+f"(c[2]), "+f"(c[3])
        : "r"(a[0]), "r"(a[1]), "r"(a[2]), "r"(a[3]), "r"(b0), "r"(b1));
}

__device__ __forceinline__ unsigned pack_bf(float lo, float hi) {
    __nv_bfloat162 h = __floats2bfloat162_rn(lo, hi);
    return *reinterpret_cast<unsigned*>(&h);
}

// ---------------- zero scratch ----------------
__global__ void zero_kernel() {
    for (int i = blockIdx.x * blockDim.x + threadIdx.x; i < MROWS * D_;
         i += gridDim.x * blockDim.x)
        g_U[i] = 0.f;
    if (blockIdx.x == 0 && threadIdx.x < 8) g_scal[threadIdx.x] = 0.f;
}

// ---------------- fused split-K bf16 GEMM: U += exp(X) @ W ----------------
__device__ __forceinline__ void issue_tile(
    const float* __restrict__ X, const float* __restrict__ W,
    float* sXf, float* sWf, int kt, int t1, int bm, int bn, int tid)
{
    if (kt < t1) {
        const int k0 = kt * BK;
        float* dX = sXf + (kt % 3) * SX_STRIDE;
        float* dW = sWf + (kt % 3) * SW_STRIDE;
        if (k0 + BK <= V_) {
            #pragma unroll
            for (int i = 0; i < 16; ++i) {
                int e = tid + i * NTHREADS;
                int row = e >> 5, col = e & 31;
                cp_async4(dX + e, X + (size_t)(bm + row) * V_ + k0 + col);
            }
            #pragma unroll
            for (int i = 0; i < 2; ++i) {
                int c = tid + i * NTHREADS;
                int k = c >> 5, n16 = c & 31;
                cp_async16(dW + k * 132 + n16 * 4,
                           W + (size_t)(k0 + k) * D_ + bn + n16 * 4);
            }
        } else {   // partial last tile: direct guarded loads, zero pad
            #pragma unroll
            for (int i = 0; i < 16; ++i) {
                int e = tid + i * NTHREADS;
                int row = e >> 5, col = e & 31;
                float v = 0.f;
                if (k0 + col < V_) v = __ldg(X + (size_t)(bm + row) * V_ + k0 + col);
                dX[e] = v;
            }
            #pragma unroll
            for (int i = 0; i < 8; ++i) {
                int p = tid + i * NTHREADS;
                int k = p >> 7, n = p & 127;
                float v = 0.f;
                if (k0 + k < V_) v = __ldg(W + (size_t)(k0 + k) * D_ + bn + n);
                dW[k * 132 + n] = v;
            }
        }
    }
    cp_commit();   // empty group if kt >= t1 — keeps wait_group accounting simple
}

__global__ __launch_bounds__(NTHREADS, 1) void gemm_fused(
    const float* __restrict__ X, const float* __restrict__ W)
{
    extern __shared__ char smem[];
    float* sXf = (float*)smem;
    float* sWf = (float*)(smem + OFF_SW);
    __nv_bfloat16 (*sA)[40] = (__nv_bfloat16(*)[40])(smem + OFF_SA);

    const int bm = blockIdx.y * BM;
    const int bn = blockIdx.x * BN;
    const int t0 = blockIdx.z * TPS;
    const int t1 = min(KT2, t0 + TPS);
    const int tid = threadIdx.x;
    const int warp = tid >> 5, lane = tid & 31;
    const int wm = (warp & 3) * 64;
    const int wn = (warp >> 2) * 32;
    const int g = lane >> 2, q = lane & 3;
    const int lm = lane & 15;            // ldmatrix row within 16
    const int lk = (lane >> 4) * 8;      // ldmatrix col half

    const uint32_t sA_u32 = (uint32_t)__cvta_generic_to_shared(&sA[0][0]);

    float acc[4][4][4];
    #pragma unroll
    for (int i = 0; i < 4; i++)
        #pragma unroll
        for (int j = 0; j < 4; j++)
            #pragma unroll
            for (int k = 0; k < 4; k++) acc[i][j][k] = 0.f;

    issue_tile(X, W, sXf, sWf, t0,     t1, bm, bn, tid);
    issue_tile(X, W, sXf, sWf, t0 + 1, t1, bm, bn, tid);

    for (int kt = t0; kt < t1; ++kt) {
        cp_wait1();
        __syncthreads();

        // --- convert X tile: fp32 -> exp -> bf16 smem ---
        {
            const float* sX = sXf + (kt % 3) * SX_STRIDE;
            #pragma unroll
            for (int i = 0; i < 8; ++i) {
                int idx = tid + i * NTHREADS;            // pair index, 4096 pairs
                float2 v = *(const float2*)(sX + idx * 2);
                __nv_bfloat162 h = __floats2bfloat162_rn(__expf(v.x), __expf(v.y));
                *(__nv_bfloat162*)&sA[idx >> 4][(idx & 15) * 2] = h;
            }
        }
        __syncthreads();

        // prefetch tile kt+2 into buffer (kt+2)%3 — disjoint from kt%3 being read
        issue_tile(X, W, sXf, sWf, kt + 2, t1, bm, bn, tid);

        // --- mma ---
        const float* sW = sWf + (kt % 3) * SW_STRIDE;
        #pragma unroll
        for (int kk = 0; kk < 2; ++kk) {
            const int kb = kk * 16 + q * 2;
            unsigned af[4][4];
            #pragma unroll
            for (int mf = 0; mf < 4; ++mf) {
                uint32_t addr = sA_u32 +
                    (uint32_t)(((wm + mf * 16 + lm) * 40 + kk * 16 + lk) * 2);
                ldmatrix_x4(af[mf], addr);
            }
            #pragma unroll
            for (int nf = 0; nf < 4; ++nf) {
                const int n = wn + nf * 8 + g;
                const float* wp = sW + kb * 132 + n;
                unsigned b0 = pack_bf(wp[0],        wp[132]);
                unsigned b1 = pack_bf(wp[132 * 8],  wp[132 * 9]);
                #pragma unroll
                for (int mf = 0; mf < 4; ++mf)
                    mma16816(acc[mf][nf], af[mf], b0, b1);
            }
        }
    }

    #pragma unroll
    for (int mf = 0; mf < 4; ++mf) {
        int r0 = bm + wm + mf * 16 + g;
        #pragma unroll
        for (int nf = 0; nf < 4; ++nf) {
            int c0 = bn + wn + nf * 8 + q * 2;
            atomicAdd(&g_U[r0 * D_ + c0],           acc[mf][nf][0]);
            atomicAdd(&g_U[r0 * D_ + c0 + 1],       acc[mf][nf][1]);
            atomicAdd(&g_U[(r0 + 8) * D_ + c0],     acc[mf][nf][2]);
            atomicAdd(&g_U[(r0 + 8) * D_ + c0 + 1], acc[mf][nf][3]);
        }
    }
}

// ---------------- coverage + NLL fused ----------------
__global__ void covnll_kernel(const float* __restrict__ attn,
                              const float* __restrict__ covg,
                              const int* __restrict__ mask,
                              const float* __restrict__ X,
                              const int* __restrict__ trg) {
    if (blockIdx.x < 128) {
        float s = 0.f;
        const int total = Bb_ * LSRC * T_;   // 262144
        for (int idx = blockIdx.x * blockDim.x + threadIdx.x; idx < total;
             idx += 128 * blockDim.x) {
            int t = idx & (T_ - 1);
            int b = idx >> 16;
            if (mask[(b << 7) + t] == 0) s += fminf(attn[idx], covg[idx]);
        }
        s = warp_sum(s);
        __shared__ float sm[8];
        int warp = threadIdx.x >> 5, lane = threadIdx.x & 31;
        if (lane == 0) sm[warp] = s;
        __syncthreads();
        if (threadIdx.x == 0) {
            float tot = 0.f;
            for (int w = 0; w < (int)(blockDim.x >> 5); ++w) tot += sm[w];
            atomicAdd(&g_scal[0], tot);
        }
    } else {
        float s = 0.f, c = 0.f;
        #pragma unroll
        for (int r = 0; r < 2; ++r) {
            int i = threadIdx.x + r * 256;
            int tg = trg[i];
            if (tg != 0) {
                s += logf(X[(size_t)i * V_ + tg]);
                c += 1.f;
            }
        }
        s = warp_sum(s);
        c = warp_sum(c);
        __shared__ float sms[8], smc[8];
        int warp = threadIdx.x >> 5, lane = threadIdx.x & 31;
        if (lane == 0) { sms[warp] = s; smc[warp] = c; }
        __syncthreads();
        if (threadIdx.x == 0) {
            float ts = 0.f, tc = 0.f;
            for (int w = 0; w < 8; ++w) { ts += sms[w]; tc += smc[w]; }
            atomicAdd(&g_scal[1], ts);
            atomicAdd(&g_scal[2], tc);
        }
    }
}

// ---------------- per-row cosine (OT via diagonal-IPOT collapse) ----------------
__global__ void finalize_kernel(const int* __restrict__ trg, const float* __restrict__ W) {
    int i = blockIdx.x;
    int tid = threadIdx.x;
    int tg = trg[i];
    const float* U = &g_U[i * D_];
    const float* E = &W[(size_t)tg * D_];
    float sue = 0.f, suu = 0.f, see = 0.f;
    for (int d = tid; d < D_; d += 128) {
        float u = U[d], e = E[d];
        sue += u * e; suu += u * u; see += e * e;
    }
    sue = warp_sum(sue); suu = warp_sum(suu); see = warp_sum(see);
    __shared__ float sm[3][4];
    int warp = tid >> 5, lane = tid & 31;
    if (lane == 0) { sm[0][warp] = sue; sm[1][warp] = suu; sm[2][warp] = see; }
    __syncthreads();
    if (tid == 0) {
        float a = sm[0][0] + sm[0][1] + sm[0][2] + sm[0][3];
        float b = sm[1][0] + sm[1][1] + sm[1][2] + sm[1][3];
        float c = sm[2][0] + sm[2][1] + sm[2][2] + sm[2][3];
        atomicAdd(&g_scal[3], a * rsqrtf(b * c));
    }
}

// ---------------- combine ----------------
__global__ void combine_kernel(const int* __restrict__ dec_len, float* __restrict__ out) {
    int ls = dec_len[0] + dec_len[1] + dec_len[2] + dec_len[3];
    float nll = -g_scal[1] / g_scal[2];
    float cov_loss = g_scal[0] / (float)ls;
    float ot = g_scal[3] / (float)MROWS;
    out[0] = nll + 1.0f * cov_loss + 0.1f + ot;
}

extern "C" void kernel_launch(void* const* d_in, const int* in_sizes, int n_in,
                              void* d_out, int out_size) {
    const float* X    = (const float*)d_in[0];
    const float* attn = (const float*)d_in[1];
    const float* covg = (const float*)d_in[2];
    const int*   trg  = (const int*)d_in[3];
    const int*   mask = (const int*)d_in[4];
    const int*   dlen = (const int*)d_in[5];
    const float* W    = (const float*)d_in[6];
    float* out = (float*)d_out;

    cudaFuncSetAttribute(gemm_fused, cudaFuncAttributeMaxDynamicSharedMemorySize,
                         SMEM_BYTES);

    zero_kernel<<<256, 256>>>();
    covnll_kernel<<<129, 256>>>(attn, covg, mask, X, trg);
    {
        dim3 grid(4, 2, KSL);   // n-blocks, m-blocks, k-slices = 144 CTAs
        gemm_fused<<<grid, NTHREADS, SMEM_BYTES>>>(X, W);
    }
    finalize_kernel<<<512, 128>>>(trg, W);
    combine_kernel<<<1, 1>>>(dlen, out);
}

// round 6
// speedup vs baseline: 1.6585x; 1.0344x over previous
#include <cuda_runtime.h>
#include <cuda_bf16.h>
#include <stdint.h>

// Problem constants
#define Bb_  4
#define T_   128
#define V_   50257
#define LSRC 512
#define D_   512
#define MROWS 512              // B*T

// GEMM tiling: 128x256 CTA tile, BK=32, 512 threads, split-K 18
#define BM 128
#define BN 256
#define BK 32
#define NT 512
#define KT2 1571               // ceil(50257/32)
#define KSL 18                 // grid: 2 n-blocks * 4 m-blocks * 18 = 144 CTAs
#define TPS 88                 // ceil(1571/18)

// dynamic smem layout (bytes)
#define WSTAGE_F (32*264)                 // floats per W fp32 stage
#define OFF_SA   67584                    // 2 * 33792
#define OFF_SB   (OFF_SA + 128*40*2)      // 67584 + 10240 = 77824
#define SMEM_BYTES (OFF_SB + 32*264*2)    // 77824 + 16896 = 94720

__device__ float g_Upart[KSL][MROWS * D_];   // split-K partials (every elem written)
__device__ float g_scal[8];                   // 0:cov 1:nll 2:valid 3:cos

__device__ __forceinline__ float warp_sum(float v) {
    #pragma unroll
    for (int o = 16; o > 0; o >>= 1) v += __shfl_xor_sync(0xffffffffu, v, o);
    return v;
}

__device__ __forceinline__ void cp_async16(void* dst, const void* src) {
    uint32_t d = (uint32_t)__cvta_generic_to_shared(dst);
    asm volatile("cp.async.cg.shared.global [%0], [%1], 16;\n" :: "r"(d), "l"(src));
}
__device__ __forceinline__ void cp_commit() {
    asm volatile("cp.async.commit_group;\n" ::: "memory");
}
__device__ __forceinline__ void cp_wait1() {
    asm volatile("cp.async.wait_group 1;\n" ::: "memory");
}
__device__ __forceinline__ void ldmatrix_x4(unsigned* r, uint32_t addr) {
    asm volatile("ldmatrix.sync.aligned.m8n8.x4.shared.b16 {%0,%1,%2,%3}, [%4];"
                 : "=r"(r[0]), "=r"(r[1]), "=r"(r[2]), "=r"(r[3]) : "r"(addr));
}
__device__ __forceinline__ void ldmatrix_x4_trans(unsigned* r, uint32_t addr) {
    asm volatile("ldmatrix.sync.aligned.m8n8.x4.trans.shared.b16 {%0,%1,%2,%3}, [%4];"
                 : "=r"(r[0]), "=r"(r[1]), "=r"(r[2]), "=r"(r[3]) : "r"(addr));
}
__device__ __forceinline__ void mma16816(float* c, const unsigned* a, unsigned b0, unsigned b1) {
    asm volatile(
        "mma.sync.aligned.m16n8k16.row.col.f32.bf16.bf16.f32 "
        "{%0,%1,%2,%3}, {%4,%5,%6,%7}, {%8,%9}, {%0,%1,%2,%3};\n"
        : "+f"(c[0]), "+f"(c[1]), "+f"(c[2]), "+f"(c[3])
        : "r"(a[0]), "r"(a[1]), "r"(a[2]), "r"(a[3]), "r"(b0), "r"(b1));
}

// ---------------- zero scalars ----------------
__global__ void zero_kernel() {
    if (threadIdx.x < 8) g_scal[threadIdx.x] = 0.f;
}

// ---------------- fused split-K bf16 GEMM: Upart[z] = exp(X) @ W (k-slice z) ----------------
__global__ __launch_bounds__(NT, 1) void gemm_fused(
    const float* __restrict__ X, const float* __restrict__ W)
{
    extern __shared__ char smem[];
    float* wbuf = (float*)smem;                                  // [2][32*264] fp32
    __nv_bfloat16* sA = (__nv_bfloat16*)(smem + OFF_SA);         // [128][40]
    __nv_bfloat16* sB = (__nv_bfloat16*)(smem + OFF_SB);         // [32][264] k-major

    const int bn = blockIdx.x * BN;
    const int bm = blockIdx.y * BM;
    const int t0 = blockIdx.z * TPS;
    const int t1 = min(KT2, t0 + TPS);
    const int tid = threadIdx.x;
    const int warp = tid >> 5, lane = tid & 31;
    const int wm = (warp & 3) * 32;      // 4 m-warps
    const int wn = (warp >> 2) * 64;     // 4 n-warps
    const int g = lane >> 2, q = lane & 3;
    const int lm16 = lane & 15, lkh = (lane >> 4) * 8;
    const int bmm = lane >> 3, br = lane & 7;   // trans-ldmatrix lane decomposition

    const uint32_t sAu = (uint32_t)__cvta_generic_to_shared(sA);
    const uint32_t sBu = (uint32_t)__cvta_generic_to_shared(sB);

    // X register-prefetch mapping: 4 threads per row, 8 consecutive k each
    const int xrow = tid >> 2;
    const int xcol = (tid & 3) * 8;

    float acc[2][8][4];
    #pragma unroll
    for (int i = 0; i < 2; i++)
        #pragma unroll
        for (int j = 0; j < 8; j++)
            #pragma unroll
            for (int k = 0; k < 4; k++) acc[i][j][k] = 0.f;

    float xr[8];

    // ---- helpers (inlined) ----
    auto issueW = [&](int kt) {
        if (kt < t1) {
            const int k0 = kt * BK;
            float* dst = wbuf + (kt & 1) * WSTAGE_F;
            if (k0 + BK <= V_) {
                #pragma unroll
                for (int i = 0; i < 4; ++i) {
                    int c = tid + i * NT;
                    int k = c >> 6, n4 = (c & 63) * 4;
                    cp_async16(dst + k * 264 + n4,
                               W + (size_t)(k0 + k) * D_ + bn + n4);
                }
            } else {
                #pragma unroll
                for (int i = 0; i < 4; ++i) {
                    int c = tid + i * NT;
                    int k = c >> 6, n4 = (c & 63) * 4;
                    float4 v = make_float4(0.f, 0.f, 0.f, 0.f);
                    if (k0 + k < V_)
                        v = *(const float4*)(W + (size_t)(k0 + k) * D_ + bn + n4);
                    *(float4*)(dst + k * 264 + n4) = v;
                }
            }
        }
        cp_commit();
    };
    auto ldgX = [&](int kt) {
        if (kt >= t1) return;
        const int k0 = kt * BK;
        const float* p = X + (size_t)(bm + xrow) * V_ + k0 + xcol;
        if (k0 + BK <= V_) {
            #pragma unroll
            for (int j = 0; j < 8; ++j) xr[j] = __ldg(p + j);
        } else {
            #pragma unroll
            for (int j = 0; j < 8; ++j)
                xr[j] = (k0 + xcol + j < V_) ? __ldg(p + j) : 0.f;
        }
    };

    // ---- prologue ----
    issueW(t0);
    issueW(t0 + 1);
    ldgX(t0);

    for (int kt = t0; kt < t1; ++kt) {
        cp_wait1();
        __syncthreads();   // W stage ready; previous mma done reading sA/sB

        // convert X (regs) -> exp -> bf16 sA
        {
            __nv_bfloat162 h[4];
            #pragma unroll
            for (int j = 0; j < 4; ++j)
                h[j] = __floats2bfloat162_rn(__expf(xr[2 * j]), __expf(xr[2 * j + 1]));
            *(uint4*)&sA[xrow * 40 + xcol] = *(uint4*)h;
        }
        // convert W fp32 stage -> bf16 sB (k-major)
        {
            const float* src = wbuf + (kt & 1) * WSTAGE_F;
            int k = tid >> 4, n16 = (tid & 15) * 16;
            const float* s = src + k * 264 + n16;
            float4 v0 = *(const float4*)(s);
            float4 v1 = *(const float4*)(s + 4);
            float4 v2 = *(const float4*)(s + 8);
            float4 v3 = *(const float4*)(s + 12);
            __nv_bfloat162 h[8];
            h[0] = __floats2bfloat162_rn(v0.x, v0.y); h[1] = __floats2bfloat162_rn(v0.z, v0.w);
            h[2] = __floats2bfloat162_rn(v1.x, v1.y); h[3] = __floats2bfloat162_rn(v1.z, v1.w);
            h[4] = __floats2bfloat162_rn(v2.x, v2.y); h[5] = __floats2bfloat162_rn(v2.z, v2.w);
            h[6] = __floats2bfloat162_rn(v3.x, v3.y); h[7] = __floats2bfloat162_rn(v3.z, v3.w);
            *(uint4*)&sB[k * 264 + n16]     = *(uint4*)&h[0];
            *(uint4*)&sB[k * 264 + n16 + 8] = *(uint4*)&h[4];
        }
        __syncthreads();

        // prefetch next X tile into regs; next-next W stage via cp.async
        ldgX(kt + 1);
        issueW(kt + 2);

        // ---- mma ----
        #pragma unroll
        for (int kk = 0; kk < 2; ++kk) {
            unsigned a0[2][4];
            #pragma unroll
            for (int mf = 0; mf < 2; ++mf) {
                uint32_t addr = sAu +
                    (uint32_t)(((wm + mf * 16 + lm16) * 40 + kk * 16 + lkh) * 2);
                ldmatrix_x4(a0[mf], addr);
            }
            #pragma unroll
            for (int p = 0; p < 4; ++p) {
                unsigned bfr[4];
                int ksrc = kk * 16 + (bmm & 1) * 8 + br;
                int nsrc = wn + p * 16 + (bmm >> 1) * 8;
                ldmatrix_x4_trans(bfr, sBu + (uint32_t)((ksrc * 264 + nsrc) * 2));
                #pragma unroll
                for (int mf = 0; mf < 2; ++mf) {
                    mma16816(acc[mf][2 * p],     a0[mf], bfr[0], bfr[1]);
                    mma16816(acc[mf][2 * p + 1], a0[mf], bfr[2], bfr[3]);
                }
            }
        }
    }

    // ---- epilogue: plain stores to this slice's partial buffer ----
    float* up = g_Upart[blockIdx.z];
    #pragma unroll
    for (int mf = 0; mf < 2; ++mf) {
        int r0 = bm + wm + mf * 16 + g;
        #pragma unroll
        for (int nf = 0; nf < 8; ++nf) {
            int c0 = bn + wn + nf * 8 + q * 2;
            *(float2*)&up[r0 * D_ + c0]       = make_float2(acc[mf][nf][0], acc[mf][nf][1]);
            *(float2*)&up[(r0 + 8) * D_ + c0] = make_float2(acc[mf][nf][2], acc[mf][nf][3]);
        }
    }
}

// ---------------- coverage + NLL fused ----------------
__global__ void covnll_kernel(const float* __restrict__ attn,
                              const float* __restrict__ covg,
                              const int* __restrict__ mask,
                              const float* __restrict__ X,
                              const int* __restrict__ trg) {
    if (blockIdx.x < 128) {
        float s = 0.f;
        const int total = Bb_ * LSRC * T_;   // 262144
        for (int idx = blockIdx.x * blockDim.x + threadIdx.x; idx < total;
             idx += 128 * blockDim.x) {
            int t = idx & (T_ - 1);
            int b = idx >> 16;
            if (mask[(b << 7) + t] == 0) s += fminf(attn[idx], covg[idx]);
        }
        s = warp_sum(s);
        __shared__ float sm[8];
        int warp = threadIdx.x >> 5, lane = threadIdx.x & 31;
        if (lane == 0) sm[warp] = s;
        __syncthreads();
        if (threadIdx.x == 0) {
            float tot = 0.f;
            for (int w = 0; w < (int)(blockDim.x >> 5); ++w) tot += sm[w];
            atomicAdd(&g_scal[0], tot);
        }
    } else {
        float s = 0.f, c = 0.f;
        #pragma unroll
        for (int r = 0; r < 2; ++r) {
            int i = threadIdx.x + r * 256;
            int tg = trg[i];
            if (tg != 0) {
                s += logf(X[(size_t)i * V_ + tg]);
                c += 1.f;
            }
        }
        s = warp_sum(s);
        c = warp_sum(c);
        __shared__ float sms[8], smc[8];
        int warp = threadIdx.x >> 5, lane = threadIdx.x & 31;
        if (lane == 0) { sms[warp] = s; smc[warp] = c; }
        __syncthreads();
        if (threadIdx.x == 0) {
            float ts = 0.f, tc = 0.f;
            for (int w = 0; w < 8; ++w) { ts += sms[w]; tc += smc[w]; }
            atomicAdd(&g_scal[1], ts);
            atomicAdd(&g_scal[2], tc);
        }
    }
}

// ------- per-row cosine (OT via diagonal-IPOT collapse) + split-K reduce -------
__global__ void finalize_kernel(const int* __restrict__ trg, const float* __restrict__ W) {
    int i = blockIdx.x;                  // 512 rows
    int tid = threadIdx.x;               // 128 threads
    int tg = trg[i];
    const float* E = &W[(size_t)tg * D_];
    float sue = 0.f, suu = 0.f, see = 0.f;
    for (int d = tid; d < D_; d += 128) {
        float u = 0.f;
        #pragma unroll
        for (int s = 0; s < KSL; ++s) u += g_Upart[s][i * D_ + d];
        float e = E[d];
        sue += u * e; suu += u * u; see += e * e;
    }
    sue = warp_sum(sue); suu = warp_sum(suu); see = warp_sum(see);
    __shared__ float sm[3][4];
    int warp = tid >> 5, lane = tid & 31;
    if (lane == 0) { sm[0][warp] = sue; sm[1][warp] = suu; sm[2][warp] = see; }
    __syncthreads();
    if (tid == 0) {
        float a = sm[0][0] + sm[0][1] + sm[0][2] + sm[0][3];
        float b = sm[1][0] + sm[1][1] + sm[1][2] + sm[1][3];
        float c = sm[2][0] + sm[2][1] + sm[2][2] + sm[2][3];
        atomicAdd(&g_scal[3], a * rsqrtf(b * c));
    }
}

// ---------------- combine ----------------
__global__ void combine_kernel(const int* __restrict__ dec_len, float* __restrict__ out) {
    int ls = dec_len[0] + dec_len[1] + dec_len[2] + dec_len[3];
    float nll = -g_scal[1] / g_scal[2];
    float cov_loss = g_scal[0] / (float)ls;
    float ot = g_scal[3] / (float)MROWS;
    out[0] = nll + 1.0f * cov_loss + 0.1f + ot;
}

extern "C" void kernel_launch(void* const* d_in, const int* in_sizes, int n_in,
                              void* d_out, int out_size) {
    const float* X    = (const float*)d_in[0];
    const float* attn = (const float*)d_in[1];
    const float* covg = (const float*)d_in[2];
    const int*   trg  = (const int*)d_in[3];
    const int*   mask = (const int*)d_in[4];
    const int*   dlen = (const int*)d_in[5];
    const float* W    = (const float*)d_in[6];
    float* out = (float*)d_out;

    cudaFuncSetAttribute(gemm_fused, cudaFuncAttributeMaxDynamicSharedMemorySize,
                         SMEM_BYTES);

    zero_kernel<<<1, 32>>>();
    covnll_kernel<<<129, 256>>>(attn, covg, mask, X, trg);
    {
        dim3 grid(2, 4, KSL);   // n-blocks, m-blocks, k-slices = 144 CTAs
        gemm_fused<<<grid, NT, SMEM_BYTES>>>(X, W);
    }
    finalize_kernel<<<512, 128>>>(trg, W);
    combine_kernel<<<1, 1>>>(dlen, out);
}

// round 7
// speedup vs baseline: 2.3941x; 1.4435x over previous
#include <cuda_runtime.h>
#include <cuda_bf16.h>
#include <stdint.h>

// Problem constants
#define Bb_  4
#define T_   128
#define V_   50257
#define LSRC 512
#define D_   512
#define MROWS 512              // B*T

// GEMM tiling: 128x256 CTA tile, BK=32, 512 threads, split-K 18
#define BM 128
#define BN 256
#define BK 32
#define NT 512
#define KT2 1571               // ceil(50257/32)
#define KSL 18                 // grid: 2 n-blocks * 4 m-blocks * 18 = 144 CTAs
#define TPS 88                 // ceil(1571/18)

#define WSTAGE_F (32*264)                  // floats per fp32 W stage
#define SAST (128*40)                      // bf16 elems per sA buffer
#define SBST (32*264)                      // bf16 elems per sB buffer
#define OFF_SA (3*WSTAGE_F*4)              // 101376
#define OFF_SB (OFF_SA + 2*SAST*2)         // 101376 + 20480 = 121856
#define SMEM_BYTES (OFF_SB + 2*SBST*2)     // 121856 + 33792 = 155648

__device__ float g_Upart[KSL][MROWS * D_];   // split-K partials (every elem written)
__device__ float g_scal[8];                   // 0:cov 1:nll 2:valid 3:cos

__device__ __forceinline__ float warp_sum(float v) {
    #pragma unroll
    for (int o = 16; o > 0; o >>= 1) v += __shfl_xor_sync(0xffffffffu, v, o);
    return v;
}
__device__ __forceinline__ void cp_async16(void* dst, const void* src) {
    uint32_t d = (uint32_t)__cvta_generic_to_shared(dst);
    asm volatile("cp.async.cg.shared.global [%0], [%1], 16;\n" :: "r"(d), "l"(src));
}
__device__ __forceinline__ void cp_commit() {
    asm volatile("cp.async.commit_group;\n" ::: "memory");
}
__device__ __forceinline__ void cp_wait1() {
    asm volatile("cp.async.wait_group 1;\n" ::: "memory");
}
__device__ __forceinline__ void ldmatrix_x4(unsigned* r, uint32_t addr) {
    asm volatile("ldmatrix.sync.aligned.m8n8.x4.shared.b16 {%0,%1,%2,%3}, [%4];"
                 : "=r"(r[0]), "=r"(r[1]), "=r"(r[2]), "=r"(r[3]) : "r"(addr));
}
__device__ __forceinline__ void ldmatrix_x4_trans(unsigned* r, uint32_t addr) {
    asm volatile("ldmatrix.sync.aligned.m8n8.x4.trans.shared.b16 {%0,%1,%2,%3}, [%4];"
                 : "=r"(r[0]), "=r"(r[1]), "=r"(r[2]), "=r"(r[3]) : "r"(addr));
}
__device__ __forceinline__ void mma16816(float* c, const unsigned* a, unsigned b0, unsigned b1) {
    asm volatile(
        "mma.sync.aligned.m16n8k16.row.col.f32.bf16.bf16.f32 "
        "{%0,%1,%2,%3}, {%4,%5,%6,%7}, {%8,%9}, {%0,%1,%2,%3};\n"
        : "+f"(c[0]), "+f"(c[1]), "+f"(c[2]), "+f"(c[3])
        : "r"(a[0]), "r"(a[1]), "r"(a[2]), "r"(a[3]), "r"(b0), "r"(b1));
}
__device__ __forceinline__ unsigned packbf(float lo, float hi) {
    __nv_bfloat162 h = __floats2bfloat162_rn(lo, hi);
    return *reinterpret_cast<unsigned*>(&h);
}

// ---------------- zero scalars ----------------
__global__ void zero_kernel() {
    if (threadIdx.x < 8) g_scal[threadIdx.x] = 0.f;
}

// ------- fused split-K bf16 GEMM: Upart[z] = exp(X) @ W (k-slice z), pipelined -------
__global__ __launch_bounds__(NT, 1) void gemm_fused(
    const float* __restrict__ X, const float* __restrict__ W)
{
    extern __shared__ char smem[];
    float* wbuf = (float*)smem;                                  // [3][32*264] fp32
    __nv_bfloat16* sA = (__nv_bfloat16*)(smem + OFF_SA);         // [2][128][40]
    __nv_bfloat16* sB = (__nv_bfloat16*)(smem + OFF_SB);         // [2][32][264] k-major

    const int bn = blockIdx.x * BN;
    const int bm = blockIdx.y * BM;
    const int t0 = blockIdx.z * TPS;
    const int t1 = min(KT2, t0 + TPS);
    const int tid = threadIdx.x;
    const int warp = tid >> 5, lane = tid & 31;
    const int wm = (warp & 3) * 32;      // 4 m-warps
    const int wn = (warp >> 2) * 64;     // 4 n-warps
    const int g = lane >> 2, q = lane & 3;
    const int lm16 = lane & 15, lkh = (lane >> 4) * 8;
    const int bmm = lane >> 3, br = lane & 7;

    const uint32_t sAu = (uint32_t)__cvta_generic_to_shared(sA);
    const uint32_t sBu = (uint32_t)__cvta_generic_to_shared(sB);

    const int xrow = tid >> 2;
    const int xcol = (tid & 3) * 8;

    float acc[2][8][4];
    #pragma unroll
    for (int i = 0; i < 2; i++)
        #pragma unroll
        for (int j = 0; j < 8; j++)
            #pragma unroll
            for (int k = 0; k < 4; k++) acc[i][j][k] = 0.f;

    float xr[8];
    unsigned xh[4];

    auto issueW = [&](int kt) {
        if (kt < t1) {
            const int k0 = kt * BK;
            float* dst = wbuf + (kt % 3) * WSTAGE_F;
            if (k0 + BK <= V_) {
                #pragma unroll
                for (int i = 0; i < 4; ++i) {
                    int c = tid + i * NT;
                    int k = c >> 6, n4 = (c & 63) * 4;
                    cp_async16(dst + k * 264 + n4,
                               W + (size_t)(k0 + k) * D_ + bn + n4);
                }
            } else {
                #pragma unroll
                for (int i = 0; i < 4; ++i) {
                    int c = tid + i * NT;
                    int k = c >> 6, n4 = (c & 63) * 4;
                    float4 v = make_float4(0.f, 0.f, 0.f, 0.f);
                    if (k0 + k < V_)
                        v = *(const float4*)(W + (size_t)(k0 + k) * D_ + bn + n4);
                    *(float4*)(dst + k * 264 + n4) = v;
                }
            }
        }
        cp_commit();
    };
    auto ldgX = [&](int kt) {
        if (kt >= t1) return;
        const int k0 = kt * BK;
        const float* p = X + (size_t)(bm + xrow) * V_ + k0 + xcol;
        if (k0 + BK <= V_) {
            #pragma unroll
            for (int j = 0; j < 8; ++j) xr[j] = __ldg(p + j);
        } else {
            #pragma unroll
            for (int j = 0; j < 8; ++j)
                xr[j] = (k0 + xcol + j < V_) ? __ldg(p + j) : 0.f;
        }
    };
    auto expX = [&]() {
        #pragma unroll
        for (int j = 0; j < 4; ++j)
            xh[j] = packbf(__expf(xr[2 * j]), __expf(xr[2 * j + 1]));
    };
    auto convX = [&](int kt) {   // xh -> sA[kt&1]
        __nv_bfloat16* dstA = sA + (kt & 1) * SAST;
        *(uint4*)&dstA[xrow * 40 + xcol] = *(uint4*)xh;
    };
    auto convW = [&](int kt) {   // own-copied wbuf stage -> sB[kt&1]
        const float* src = wbuf + (kt % 3) * WSTAGE_F;
        __nv_bfloat16* dstB = sB + (kt & 1) * SBST;
        #pragma unroll
        for (int i = 0; i < 4; ++i) {
            int c = tid + i * NT;
            int k = c >> 6, n4 = (c & 63) * 4;
            float4 v = *(const float4*)(src + k * 264 + n4);
            uint2 u = make_uint2(packbf(v.x, v.y), packbf(v.z, v.w));
            *(uint2*)&dstB[k * 264 + n4] = u;
        }
    };

    // ---- prologue: fill buffers for tile t0, prefetch t0+1 ----
    issueW(t0);
    issueW(t0 + 1);
    ldgX(t0);
    cp_wait1();             // own group t0 complete
    expX();
    convX(t0);
    convW(t0);
    ldgX(t0 + 1);
    issueW(t0 + 2);
    __syncthreads();        // buffers (t0&1) visible to all

    for (int kt = t0; kt < t1; ++kt) {
        const int cur = kt & 1;
        const bool hn = (kt + 1 < t1);

        if (hn) expX();     // exp of X(kt+1); LDG latency covered by prev iteration

        // ---- mma on buffers[cur] ----
        const uint32_t sAc = sAu + (uint32_t)(cur * SAST * 2);
        const uint32_t sBc = sBu + (uint32_t)(cur * SBST * 2);
        #pragma unroll
        for (int kk = 0; kk < 2; ++kk) {
            unsigned a0[2][4];
            #pragma unroll
            for (int mf = 0; mf < 2; ++mf) {
                uint32_t addr = sAc +
                    (uint32_t)(((wm + mf * 16 + lm16) * 40 + kk * 16 + lkh) * 2);
                ldmatrix_x4(a0[mf], addr);
            }
            #pragma unroll
            for (int p = 0; p < 4; ++p) {
                unsigned bfr[4];
                int ksrc = kk * 16 + (bmm & 1) * 8 + br;
                int nsrc = wn + p * 16 + (bmm >> 1) * 8;
                ldmatrix_x4_trans(bfr, sBc + (uint32_t)((ksrc * 264 + nsrc) * 2));
                #pragma unroll
                for (int mf = 0; mf < 2; ++mf) {
                    mma16816(acc[mf][2 * p],     a0[mf], bfr[0], bfr[1]);
                    mma16816(acc[mf][2 * p + 1], a0[mf], bfr[2], bfr[3]);
                }
            }
        }

        if (hn) {
            cp_wait1();          // own cp group (kt+1) complete
            convX(kt + 1);       // write buffers[nxt]: safe vs readers via prev barrier
            convW(kt + 1);
            ldgX(kt + 2);
            issueW(kt + 3);
            __syncthreads();     // buffers[nxt] visible for next iteration
        }
    }

    // ---- epilogue: plain stores to this slice's partial buffer ----
    float* up = g_Upart[blockIdx.z];
    #pragma unroll
    for (int mf = 0; mf < 2; ++mf) {
        int r0 = bm + wm + mf * 16 + g;
        #pragma unroll
        for (int nf = 0; nf < 8; ++nf) {
            int c0 = bn + wn + nf * 8 + q * 2;
            *(float2*)&up[r0 * D_ + c0]       = make_float2(acc[mf][nf][0], acc[mf][nf][1]);
            *(float2*)&up[(r0 + 8) * D_ + c0] = make_float2(acc[mf][nf][2], acc[mf][nf][3]);
        }
    }
}

// ---------------- coverage + NLL fused ----------------
__global__ void covnll_kernel(const float* __restrict__ attn,
                              const float* __restrict__ covg,
                              const int* __restrict__ mask,
                              const float* __restrict__ X,
                              const int* __restrict__ trg) {
    if (blockIdx.x < 128) {
        float s = 0.f;
        const int total = Bb_ * LSRC * T_;   // 262144
        for (int idx = blockIdx.x * blockDim.x + threadIdx.x; idx < total;
             idx += 128 * blockDim.x) {
            int t = idx & (T_ - 1);
            int b = idx >> 16;
            if (mask[(b << 7) + t] == 0) s += fminf(attn[idx], covg[idx]);
        }
        s = warp_sum(s);
        __shared__ float sm[8];
        int warp = threadIdx.x >> 5, lane = threadIdx.x & 31;
        if (lane == 0) sm[warp] = s;
        __syncthreads();
        if (threadIdx.x == 0) {
            float tot = 0.f;
            for (int w = 0; w < (int)(blockDim.x >> 5); ++w) tot += sm[w];
            atomicAdd(&g_scal[0], tot);
        }
    } else {
        float s = 0.f, c = 0.f;
        #pragma unroll
        for (int r = 0; r < 2; ++r) {
            int i = threadIdx.x + r * 256;
            int tg = trg[i];
            if (tg != 0) {
                s += logf(X[(size_t)i * V_ + tg]);
                c += 1.f;
            }
        }
        s = warp_sum(s);
        c = warp_sum(c);
        __shared__ float sms[8], smc[8];
        int warp = threadIdx.x >> 5, lane = threadIdx.x & 31;
        if (lane == 0) { sms[warp] = s; smc[warp] = c; }
        __syncthreads();
        if (threadIdx.x == 0) {
            float ts = 0.f, tc = 0.f;
            for (int w = 0; w < 8; ++w) { ts += sms[w]; tc += smc[w]; }
            atomicAdd(&g_scal[1], ts);
            atomicAdd(&g_scal[2], tc);
        }
    }
}

// ------- per-row cosine (OT via diagonal-IPOT collapse) + split-K reduce -------
__global__ void finalize_kernel(const int* __restrict__ trg, const float* __restrict__ W) {
    int i = blockIdx.x;                  // 512 rows
    int tid = threadIdx.x;               // 128 threads
    int tg = trg[i];
    const float* E = &W[(size_t)tg * D_];
    float sue = 0.f, suu = 0.f, see = 0.f;
    for (int d = tid; d < D_; d += 128) {
        float u = 0.f;
        #pragma unroll
        for (int s = 0; s < KSL; ++s) u += g_Upart[s][i * D_ + d];
        float e = E[d];
        sue += u * e; suu += u * u; see += e * e;
    }
    sue = warp_sum(sue); suu = warp_sum(suu); see = warp_sum(see);
    __shared__ float sm[3][4];
    int warp = tid >> 5, lane = tid & 31;
    if (lane == 0) { sm[0][warp] = sue; sm[1][warp] = suu; sm[2][warp] = see; }
    __syncthreads();
    if (tid == 0) {
        float a = sm[0][0] + sm[0][1] + sm[0][2] + sm[0][3];
        float b = sm[1][0] + sm[1][1] + sm[1][2] + sm[1][3];
        float c = sm[2][0] + sm[2][1] + sm[2][2] + sm[2][3];
        atomicAdd(&g_scal[3], a * rsqrtf(b * c));
    }
}

// ---------------- combine ----------------
__global__ void combine_kernel(const int* __restrict__ dec_len, float* __restrict__ out) {
    int ls = dec_len[0] + dec_len[1] + dec_len[2] + dec_len[3];
    float nll = -g_scal[1] / g_scal[2];
    float cov_loss = g_scal[0] / (float)ls;
    float ot = g_scal[3] / (float)MROWS;
    out[0] = nll + 1.0f * cov_loss + 0.1f + ot;
}

extern "C" void kernel_launch(void* const* d_in, const int* in_sizes, int n_in,
                              void* d_out, int out_size) {
    const float* X    = (const float*)d_in[0];
    const float* attn = (const float*)d_in[1];
    const float* covg = (const float*)d_in[2];
    const int*   trg  = (const int*)d_in[3];
    const int*   mask = (const int*)d_in[4];
    const int*   dlen = (const int*)d_in[5];
    const float* W    = (const float*)d_in[6];
    float* out = (float*)d_out;

    cudaFuncSetAttribute(gemm_fused, cudaFuncAttributeMaxDynamicSharedMemorySize,
                         SMEM_BYTES);

    zero_kernel<<<1, 32>>>();
    covnll_kernel<<<129, 256>>>(attn, covg, mask, X, trg);
    {
        dim3 grid(2, 4, KSL);   // n-blocks, m-blocks, k-slices = 144 CTAs
        gemm_fused<<<grid, NT, SMEM_BYTES>>>(X, W);
    }
    finalize_kernel<<<512, 128>>>(trg, W);
    combine_kernel<<<1, 1>>>(dlen, out);
}